// round 13
// baseline (speedup 1.0000x reference)
#include <cuda_runtime.h>
#include <cuda_bf16.h>
#include <math_constants.h>

// Problem constants
#define BB 16
#define CC 3
#define MM 512
#define NN 512
#define MNP (MM * NN)                 // 262144 pixels per (b, c) plane
#define PIX (BB * MNP)                // 4,194,304 pixels
#define THREADS1 256
#define PIX_PER_THREAD 4
#define PIX_PER_BLOCK (THREADS1 * PIX_PER_THREAD)     // 1024
#define BLOCKS1 (PIX / PIX_PER_BLOCK)                 // 4096
#define SIG_TILE_BYTES (PIX_PER_BLOCK * 9 * 4)        // 36864 B per block
#define EPS_F 1e-6f
#define T1_CLIP_F 1e7f

// Fixed scratch for block partials (no allocation allowed)
__device__ float g_psum[BLOCKS1];
__device__ float g_pmax[BLOCKS1];
__device__ unsigned int g_count = 0;

__device__ __forceinline__ float rcp_approx(float x) {
    float y;
    asm("rcp.approx.f32 %0, %1;" : "=f"(y) : "f"(x));
    return y;
}

// Streaming 128-bit global load
__device__ __forceinline__ float4 ldcs4(const float* p) {
    return __ldcs(reinterpret_cast<const float4*>(p));
}

__global__ __launch_bounds__(THREADS1) void maploss_main(
    const float* __restrict__ target,
    const float* __restrict__ mu,
    const float* __restrict__ sigma_y,
    float* __restrict__ out)
{
    // Whole-block sigma tile: 1024 px * 36 B = 36 KB, filled by ONE TMA bulk copy
    __shared__ __align__(128) float s_sig[PIX_PER_BLOCK * 9];
    __shared__ __align__(8) unsigned long long s_mbar;

    const int tid  = threadIdx.x;
    const int lane = tid & 31;
    const int wid  = tid >> 5;

    const unsigned mbar_a = (unsigned)__cvta_generic_to_shared(&s_mbar);

    // ---- 1) init mbarrier, then one bulk copy of the block's sigma tile ----
    if (tid == 0) {
        asm volatile("mbarrier.init.shared.b64 [%0], 1;" :: "r"(mbar_a) : "memory");
    }
    __syncthreads();
    if (tid == 0) {
        const unsigned dst = (unsigned)__cvta_generic_to_shared(s_sig);
        const float* src = sigma_y + (size_t)blockIdx.x * PIX_PER_BLOCK * 9;
        asm volatile("mbarrier.arrive.expect_tx.shared.b64 _, [%0], %1;"
                     :: "r"(mbar_a), "r"((unsigned)SIG_TILE_BYTES) : "memory");
        asm volatile("cp.async.bulk.shared::cta.global.mbarrier::complete_tx::bytes "
                     "[%0], [%1], %2, [%3];"
                     :: "r"(dst), "l"(src), "r"((unsigned)SIG_TILE_BYTES),
                        "r"(mbar_a) : "memory");
    }

    // ---- 2) target/mu: 6 wide LDG.128 per thread (4 consecutive pixels),
    //         in flight while the bulk copy streams ----
    const int p0 = blockIdx.x * PIX_PER_BLOCK + tid * PIX_PER_THREAD;
    const int b  = p0 >> 18;
    const int r  = p0 & (MNP - 1);
    const size_t base = (size_t)b * (CC * MNP) + r;

    float4 t0 = ldcs4(target + base);
    float4 t1 = ldcs4(target + base + MNP);
    float4 t2 = ldcs4(target + base + 2 * MNP);
    float4 u0 = ldcs4(mu + base);
    float4 u1 = ldcs4(mu + base + MNP);
    float4 u2 = ldcs4(mu + base + 2 * MNP);

    const float dx[4] = { t0.x - u0.x, t0.y - u0.y, t0.z - u0.z, t0.w - u0.w };
    const float dy[4] = { t1.x - u1.x, t1.y - u1.y, t1.z - u1.z, t1.w - u1.w };
    const float dz[4] = { t2.x - u2.x, t2.y - u2.y, t2.z - u2.z, t2.w - u2.w };

    // ---- 3) wait for sigma tile (mbarrier parity 0) ----
    {
        unsigned done;
        asm volatile(
            "{\n\t"
            ".reg .pred p;\n\t"
            "mbarrier.try_wait.parity.acquire.cta.shared::cta.b64 p, [%1], 0;\n\t"
            "selp.b32 %0, 1, 0, p;\n\t"
            "}" : "=r"(done) : "r"(mbar_a) : "memory");
        if (!done) {
            asm volatile(
                "{\n\t"
                ".reg .pred P1;\n\t"
                "WL_%=:\n\t"
                "mbarrier.try_wait.parity.acquire.cta.shared::cta.b64 P1, [%0], 0, 0x989680;\n\t"
                "@P1 bra.uni WD_%=;\n\t"
                "bra.uni WL_%=;\n\t"
                "WD_%=:\n\t"
                "}" :: "r"(mbar_a) : "memory");
        }
    }

    // ---- 4) per-thread sigma slab: 36 floats at 144B stride, 9 LDS.128 ----
    const float4* s4 = reinterpret_cast<const float4*>(&s_sig[tid * 36]);
    float4 sv[9];
#pragma unroll
    for (int i = 0; i < 9; i++) sv[i] = s4[i];
    const float* sf = reinterpret_cast<const float*>(sv);

    float qv[4], dc[4];
#pragma unroll
    for (int j = 0; j < 4; j++) {
        const float* s = sf + 9 * j;   // row-major symmetric 3x3
        const float a  = s[0], bq = s[1], c = s[2];
        const float d  = s[4], e  = s[5];
        const float f  = s[8];

        const float A00 = fmaf(d, f, -e * e);
        const float A01 = fmaf(c, e, -bq * f);
        const float A02 = fmaf(bq, e, -c * d);
        const float A11 = fmaf(a, f, -c * c);
        const float A12 = fmaf(bq, c, -a * e);
        const float A22 = fmaf(a, d, -bq * bq);

        const float det = fmaf(a, A00, fmaf(bq, A01, c * A02));

        const float x = dx[j], y = dy[j], z = dz[j];
        float q = x * x * A00;
        q = fmaf(y * y, A11, q);
        q = fmaf(z * z, A22, q);
        float cross = x * y * A01;
        cross = fmaf(x * z, A02, cross);
        cross = fmaf(y * z, A12, cross);
        q = fmaf(2.0f, cross, q);

        qv[j] = q;
        dc[j] = fmaxf(det, EPS_F);   // SPD (>= 0.5 I) => clamp never binds
    }

    // ---- batched reciprocal + batched log: 1 RCP + 1 LG2 per 4 pixels ----
    const float p01  = dc[0] * dc[1];
    const float p23  = dc[2] * dc[3];
    const float prod = p01 * p23;
    const float invp = rcp_approx(prod);

    const float t1v0 = 0.5f * qv[0] * (dc[1] * p23 * invp);
    const float t1v1 = 0.5f * qv[1] * (dc[0] * p23 * invp);
    const float t1v2 = 0.5f * qv[2] * (p01 * dc[3] * invp);
    const float t1v3 = 0.5f * qv[3] * (p01 * dc[2] * invp);

    float sumv = (t1v0 + t1v1) + (t1v2 + t1v3) + 0.5f * __logf(prod);
    float maxv = fmaxf(fmaxf(t1v0, t1v1), fmaxf(t1v2, t1v3));

    // ---- warp reduce ----
#pragma unroll
    for (int off = 16; off > 0; off >>= 1) {
        sumv += __shfl_down_sync(0xFFFFFFFFu, sumv, off);
        maxv  = fmaxf(maxv, __shfl_down_sync(0xFFFFFFFFu, maxv, off));
    }

    __shared__ float ssum[THREADS1 / 32];
    __shared__ float smax[THREADS1 / 32];
    if (lane == 0) { ssum[wid] = sumv; smax[wid] = maxv; }
    __syncthreads();

    if (wid == 0) {
        float s2 = (lane < THREADS1 / 32) ? ssum[lane] : 0.0f;
        float m2 = (lane < THREADS1 / 32) ? smax[lane] : -CUDART_INF_F;
#pragma unroll
        for (int off = 4; off > 0; off >>= 1) {
            s2 += __shfl_down_sync(0xFFFFFFFFu, s2, off);
            m2  = fmaxf(m2, __shfl_down_sync(0xFFFFFFFFu, m2, off));
        }
        if (lane == 0) {
            g_psum[blockIdx.x] = s2;
            g_pmax[blockIdx.x] = m2;
        }
    }

    // ---- fused finish: last block reduces all partials ----
    __shared__ bool is_last;
    __syncthreads();
    if (threadIdx.x == 0) {
        __threadfence();        // publish this block's partials
        unsigned int old = atomicAdd(&g_count, 1u);
        is_last = (old == (unsigned int)(BLOCKS1 - 1));
    }
    __syncthreads();

    if (is_last) {
        if (threadIdx.x == 0) __threadfence();  // acquire: see all partials
        __syncthreads();
        float s = 0.0f;
        float m = -CUDART_INF_F;
#pragma unroll
        for (int i = 0; i < BLOCKS1 / THREADS1; i++) {
            const int idx = threadIdx.x + i * THREADS1;
            s += __ldcg(&g_psum[idx]);
            m  = fmaxf(m, __ldcg(&g_pmax[idx]));
        }
#pragma unroll
        for (int off = 16; off > 0; off >>= 1) {
            s += __shfl_down_sync(0xFFFFFFFFu, s, off);
            m  = fmaxf(m, __shfl_down_sync(0xFFFFFFFFu, m, off));
        }
        if (lane == 0) { ssum[wid] = s; smax[wid] = m; }
        __syncthreads();
        if (wid == 0) {
            float s2 = (lane < THREADS1 / 32) ? ssum[lane] : 0.0f;
            float m2 = (lane < THREADS1 / 32) ? smax[lane] : -CUDART_INF_F;
#pragma unroll
            for (int off = 4; off > 0; off >>= 1) {
                s2 += __shfl_down_sync(0xFFFFFFFFu, s2, off);
                m2  = fmaxf(m2, __shfl_down_sync(0xFFFFFFFFu, m2, off));
            }
            if (lane == 0) {
                const float mean = s2 * (1.0f / (float)PIX);
                out[0] = (m2 > T1_CLIP_F) ? 0.0f : mean;
                g_count = 0;   // reset ticket for next graph replay
            }
        }
    }
}

extern "C" void kernel_launch(void* const* d_in, const int* in_sizes, int n_in,
                              void* d_out, int out_size)
{
    // Input order per reference: target, mu, sigma_mu, sigma_n, sigma_y
    const float* target  = (const float*)d_in[0];
    const float* mu      = (const float*)d_in[1];
    const float* sigma_y = (const float*)d_in[4];
    float* out = (float*)d_out;

    maploss_main<<<BLOCKS1, THREADS1>>>(target, mu, sigma_y, out);
}

// round 14
// speedup vs baseline: 1.0171x; 1.0171x over previous
#include <cuda_runtime.h>
#include <cuda_bf16.h>
#include <math_constants.h>

// Problem constants
#define BB 16
#define CC 3
#define MM 512
#define NN 512
#define MNP (MM * NN)                 // 262144 pixels per (b, c) plane
#define PIX (BB * MNP)                // 4,194,304 pixels
#define THREADS1 256
#define PIX_PER_THREAD 4
#define PIX_PER_BLOCK (THREADS1 * PIX_PER_THREAD)     // 1024
#define BLOCKS1 (PIX / PIX_PER_BLOCK)                 // 4096
#define EPS_F 1e-6f
#define T1_CLIP_F 1e7f

// Fixed scratch for block partials (no allocation allowed)
__device__ float g_psum[BLOCKS1];
__device__ float g_pmax[BLOCKS1];
__device__ unsigned int g_count = 0;

__device__ __forceinline__ float rcp_approx(float x) {
    float y;
    asm("rcp.approx.f32 %0, %1;" : "=f"(y) : "f"(x));
    return y;
}

// Streaming 128-bit global load
__device__ __forceinline__ float4 ldcs4(const float* p) {
    return __ldcs(reinterpret_cast<const float4*>(p));
}

__global__ __launch_bounds__(THREADS1, 6) void maploss_main(
    const float* __restrict__ target,
    const float* __restrict__ mu,
    const float* __restrict__ sigma_y,
    float* __restrict__ out)
{
    // Warp-owned sigma staging: 8 warps * 128 px * 9 floats = 36 KB
    __shared__ float s_sig[THREADS1 * 9 * PIX_PER_THREAD];

    const int tid  = threadIdx.x;
    const int lane = tid & 31;
    const int wid  = tid >> 5;

    // Warp tile: 128 consecutive pixels; thread owns 4 CONSECUTIVE pixels.
    const int warpPixBase = blockIdx.x * PIX_PER_BLOCK + wid * 128;

    // ---- 1) target/mu first: 6 wide LDG.128 per thread, longest latency ----
    const int p0 = warpPixBase + lane * PIX_PER_THREAD;
    const int b  = p0 >> 18;
    const int r  = p0 & (MNP - 1);
    const size_t base = (size_t)b * (CC * MNP) + r;

    float4 t0 = ldcs4(target + base);
    float4 u0 = ldcs4(mu + base);
    float4 t1 = ldcs4(target + base + MNP);
    float4 u1 = ldcs4(mu + base + MNP);
    float4 t2 = ldcs4(target + base + 2 * MNP);
    float4 u2 = ldcs4(mu + base + 2 * MNP);

    // ---- 2) cp.async staging of sigma (coalesced 16B chunks) ----
    {
        const float* src = sigma_y + (size_t)warpPixBase * 9;   // 4608 B / warp
        unsigned smem_w = (unsigned)__cvta_generic_to_shared(
            &s_sig[wid * (128 * 9)]);
#pragma unroll
        for (int k = 0; k < 9; k++) {
            const int f4 = k * 32 + lane;
            asm volatile("cp.async.cg.shared.global [%0], [%1], 16;"
                         :: "r"(smem_w + f4 * 16), "l"(src + f4 * 4) : "memory");
        }
        asm volatile("cp.async.commit_group;" ::: "memory");
    }

    // Consume t/mu into differences ASAP (frees 12 registers before the wait)
    const float dx[4] = { t0.x - u0.x, t0.y - u0.y, t0.z - u0.z, t0.w - u0.w };
    const float dy[4] = { t1.x - u1.x, t1.y - u1.y, t1.z - u1.z, t1.w - u1.w };
    const float dz[4] = { t2.x - u2.x, t2.y - u2.y, t2.z - u2.z, t2.w - u2.w };

    // ---- 3) wait for sigma; per-thread 144B slab via LDS.128 (conflict-free) ----
    asm volatile("cp.async.wait_group 0;" ::: "memory");
    __syncwarp();

    // Thread's 36 sigma floats start at word 36*tid... within the warp slab:
    // 144B stride, 16B aligned -> 9 LDS.128, bank-conflict-free per phase.
    const float4* s4 = reinterpret_cast<const float4*>(
        &s_sig[wid * (128 * 9) + lane * 36]);

    float qv[4], dc[4];
#pragma unroll
    for (int j = 0; j < 4; j++) {
        // Load just this pixel's 3 float4 (9 floats + 3 pad of next pixel)
        const float4 sA = s4[(9 * j) / 4 + 0];      // not aligned per-pixel; use full slab
        (void)sA;
        const float* s = reinterpret_cast<const float*>(s4) + 9 * j;
        const float a  = s[0], bq = s[1], c = s[2];
        const float d  = s[4], e  = s[5];
        const float f  = s[8];

        const float A00 = fmaf(d, f, -e * e);
        const float A01 = fmaf(c, e, -bq * f);
        const float A02 = fmaf(bq, e, -c * d);
        const float A11 = fmaf(a, f, -c * c);
        const float A12 = fmaf(bq, c, -a * e);
        const float A22 = fmaf(a, d, -bq * bq);

        const float det = fmaf(a, A00, fmaf(bq, A01, c * A02));

        const float x = dx[j], y = dy[j], z = dz[j];
        float q = x * x * A00;
        q = fmaf(y * y, A11, q);
        q = fmaf(z * z, A22, q);
        float cross = x * y * A01;
        cross = fmaf(x * z, A02, cross);
        cross = fmaf(y * z, A12, cross);
        q = fmaf(2.0f, cross, q);

        qv[j] = q;
        dc[j] = fmaxf(det, EPS_F);   // SPD (>= 0.5 I) => clamp never binds
    }

    // ---- batched reciprocal + batched log: 1 RCP + 1 LG2 per 4 pixels ----
    const float p01  = dc[0] * dc[1];
    const float p23  = dc[2] * dc[3];
    const float prod = p01 * p23;
    const float invp = rcp_approx(prod);

    const float t1v0 = 0.5f * qv[0] * (dc[1] * p23 * invp);
    const float t1v1 = 0.5f * qv[1] * (dc[0] * p23 * invp);
    const float t1v2 = 0.5f * qv[2] * (p01 * dc[3] * invp);
    const float t1v3 = 0.5f * qv[3] * (p01 * dc[2] * invp);

    float sumv = (t1v0 + t1v1) + (t1v2 + t1v3) + 0.5f * __logf(prod);
    float maxv = fmaxf(fmaxf(t1v0, t1v1), fmaxf(t1v2, t1v3));

    // ---- warp reduce ----
#pragma unroll
    for (int off = 16; off > 0; off >>= 1) {
        sumv += __shfl_down_sync(0xFFFFFFFFu, sumv, off);
        maxv  = fmaxf(maxv, __shfl_down_sync(0xFFFFFFFFu, maxv, off));
    }

    __shared__ float ssum[THREADS1 / 32];
    __shared__ float smax[THREADS1 / 32];
    if (lane == 0) { ssum[wid] = sumv; smax[wid] = maxv; }
    __syncthreads();

    if (wid == 0) {
        float s2 = (lane < THREADS1 / 32) ? ssum[lane] : 0.0f;
        float m2 = (lane < THREADS1 / 32) ? smax[lane] : -CUDART_INF_F;
#pragma unroll
        for (int off = 4; off > 0; off >>= 1) {
            s2 += __shfl_down_sync(0xFFFFFFFFu, s2, off);
            m2  = fmaxf(m2, __shfl_down_sync(0xFFFFFFFFu, m2, off));
        }
        if (lane == 0) {
            g_psum[blockIdx.x] = s2;
            g_pmax[blockIdx.x] = m2;
        }
    }

    // ---- fused finish: last block reduces all partials ----
    __shared__ bool is_last;
    __syncthreads();
    if (tid == 0) {
        __threadfence();        // publish this block's partials
        unsigned int old = atomicAdd(&g_count, 1u);
        is_last = (old == (unsigned int)(BLOCKS1 - 1));
    }
    __syncthreads();

    if (is_last) {
        if (tid == 0) __threadfence();  // acquire: see all partials
        __syncthreads();
        float s = 0.0f;
        float m = -CUDART_INF_F;
#pragma unroll
        for (int i = 0; i < BLOCKS1 / THREADS1; i++) {
            const int idx = tid + i * THREADS1;
            s += __ldcg(&g_psum[idx]);
            m  = fmaxf(m, __ldcg(&g_pmax[idx]));
        }
#pragma unroll
        for (int off = 16; off > 0; off >>= 1) {
            s += __shfl_down_sync(0xFFFFFFFFu, s, off);
            m  = fmaxf(m, __shfl_down_sync(0xFFFFFFFFu, m, off));
        }
        if (lane == 0) { ssum[wid] = s; smax[wid] = m; }
        __syncthreads();
        if (wid == 0) {
            float s2 = (lane < THREADS1 / 32) ? ssum[lane] : 0.0f;
            float m2 = (lane < THREADS1 / 32) ? smax[lane] : -CUDART_INF_F;
#pragma unroll
            for (int off = 4; off > 0; off >>= 1) {
                s2 += __shfl_down_sync(0xFFFFFFFFu, s2, off);
                m2  = fmaxf(m2, __shfl_down_sync(0xFFFFFFFFu, m2, off));
            }
            if (lane == 0) {
                const float mean = s2 * (1.0f / (float)PIX);
                out[0] = (m2 > T1_CLIP_F) ? 0.0f : mean;
                g_count = 0;   // reset ticket for next graph replay
            }
        }
    }
}

extern "C" void kernel_launch(void* const* d_in, const int* in_sizes, int n_in,
                              void* d_out, int out_size)
{
    // Input order per reference: target, mu, sigma_mu, sigma_n, sigma_y
    const float* target  = (const float*)d_in[0];
    const float* mu      = (const float*)d_in[1];
    const float* sigma_y = (const float*)d_in[4];
    float* out = (float*)d_out;

    maploss_main<<<BLOCKS1, THREADS1>>>(target, mu, sigma_y, out);
}

// round 15
// speedup vs baseline: 1.0564x; 1.0386x over previous
#include <cuda_runtime.h>
#include <cuda_bf16.h>
#include <math_constants.h>

// Problem constants
#define BB 16
#define CC 3
#define MM 512
#define NN 512
#define MNP (MM * NN)                 // 262144 pixels per (b, c) plane
#define PIX (BB * MNP)                // 4,194,304 pixels
#define THREADS1 256
#define PIX_PER_THREAD 4
#define PIX_PER_BLOCK (THREADS1 * PIX_PER_THREAD)     // 1024
#define BLOCKS1 (PIX / PIX_PER_BLOCK)                 // 4096
#define EPS_F 1e-6f
#define T1_CLIP_F 1e7f

// Fixed scratch for block partials (no allocation allowed)
__device__ float g_psum[BLOCKS1];
__device__ float g_pmax[BLOCKS1];
__device__ unsigned int g_count = 0;

__device__ __forceinline__ float rcp_approx(float x) {
    float y;
    asm("rcp.approx.f32 %0, %1;" : "=f"(y) : "f"(x));
    return y;
}

// Streaming 128-bit global load
__device__ __forceinline__ float4 ldcs4(const float* p) {
    return __ldcs(reinterpret_cast<const float4*>(p));
}

__global__ __launch_bounds__(THREADS1) void maploss_main(
    const float* __restrict__ target,
    const float* __restrict__ mu,
    const float* __restrict__ sigma_y,
    float* __restrict__ out)
{
    // Warp-owned sigma staging: 8 warps * 128 px * 9 floats = 36 KB
    __shared__ float s_sig[THREADS1 * 9 * PIX_PER_THREAD];

    const int tid  = threadIdx.x;
    const int lane = tid & 31;
    const int wid  = tid >> 5;

    // Warp tile: 128 consecutive pixels; thread owns 4 CONSECUTIVE pixels.
    const int warpPixBase = blockIdx.x * PIX_PER_BLOCK + wid * 128;

    // ---- 1) t/mu wide loads FIRST (longest latency into the L1tex queue) ----
    const int p0 = warpPixBase + lane * PIX_PER_THREAD;
    const int b  = p0 >> 18;
    const int r  = p0 & (MNP - 1);
    const size_t base = (size_t)b * (CC * MNP) + r;

    float4 t0 = ldcs4(target + base);
    float4 u0 = ldcs4(mu + base);
    float4 t1 = ldcs4(target + base + MNP);
    float4 u1 = ldcs4(mu + base + MNP);
    float4 t2 = ldcs4(target + base + 2 * MNP);
    float4 u2 = ldcs4(mu + base + 2 * MNP);

    // ---- 2) cp.async staging of sigma (coalesced 16B chunks) ----
    {
        const float* src = sigma_y + (size_t)warpPixBase * 9;   // 4608 B / warp
        unsigned smem_w = (unsigned)__cvta_generic_to_shared(
            &s_sig[wid * (128 * 9)]);
#pragma unroll
        for (int k = 0; k < 9; k++) {
            const int f4 = k * 32 + lane;
            asm volatile("cp.async.cg.shared.global [%0], [%1], 16;"
                         :: "r"(smem_w + f4 * 16), "l"(src + f4 * 4) : "memory");
        }
        asm volatile("cp.async.commit_group;" ::: "memory");
    }

    // Fold t/mu into differences ASAP (frees 12 registers before the wait)
    const float dx[4] = { t0.x - u0.x, t0.y - u0.y, t0.z - u0.z, t0.w - u0.w };
    const float dy[4] = { t1.x - u1.x, t1.y - u1.y, t1.z - u1.z, t1.w - u1.w };
    const float dz[4] = { t2.x - u2.x, t2.y - u2.y, t2.z - u2.z, t2.w - u2.w };

    // ---- 3) wait for sigma; per-thread 144B slab via LDS.128 (conflict-free) ----
    asm volatile("cp.async.wait_group 0;" ::: "memory");
    __syncwarp();

    // Thread's 36 sigma floats start at word 36*lane within the warp slab
    // (144B stride, 16B aligned -> 9 LDS.128, bank-conflict-free per phase).
    const float4* s4 = reinterpret_cast<const float4*>(
        &s_sig[wid * (128 * 9) + lane * 36]);
    float4 sv[9];
#pragma unroll
    for (int i = 0; i < 9; i++) sv[i] = s4[i];
    const float* sf = reinterpret_cast<const float*>(sv);

    float qv[4], dc[4];
#pragma unroll
    for (int j = 0; j < 4; j++) {
        const float* s = sf + 9 * j;   // row-major symmetric 3x3
        const float a  = s[0], bq = s[1], c = s[2];
        const float d  = s[4], e  = s[5];
        const float f  = s[8];

        const float A00 = fmaf(d, f, -e * e);
        const float A01 = fmaf(c, e, -bq * f);
        const float A02 = fmaf(bq, e, -c * d);
        const float A11 = fmaf(a, f, -c * c);
        const float A12 = fmaf(bq, c, -a * e);
        const float A22 = fmaf(a, d, -bq * bq);

        const float det = fmaf(a, A00, fmaf(bq, A01, c * A02));

        const float x = dx[j], y = dy[j], z = dz[j];
        float q = x * x * A00;
        q = fmaf(y * y, A11, q);
        q = fmaf(z * z, A22, q);
        float cross = x * y * A01;
        cross = fmaf(x * z, A02, cross);
        cross = fmaf(y * z, A12, cross);
        q = fmaf(2.0f, cross, q);

        qv[j] = q;
        dc[j] = fmaxf(det, EPS_F);   // SPD (>= 0.5 I) => clamp never binds
    }

    // ---- batched reciprocal + batched log: 1 RCP + 1 LG2 per 4 pixels ----
    const float p01  = dc[0] * dc[1];
    const float p23  = dc[2] * dc[3];
    const float prod = p01 * p23;
    const float invp = rcp_approx(prod);

    const float t1v0 = 0.5f * qv[0] * (dc[1] * p23 * invp);
    const float t1v1 = 0.5f * qv[1] * (dc[0] * p23 * invp);
    const float t1v2 = 0.5f * qv[2] * (p01 * dc[3] * invp);
    const float t1v3 = 0.5f * qv[3] * (p01 * dc[2] * invp);

    float sumv = (t1v0 + t1v1) + (t1v2 + t1v3) + 0.5f * __logf(prod);
    float maxv = fmaxf(fmaxf(t1v0, t1v1), fmaxf(t1v2, t1v3));

    // ---- warp reduce ----
#pragma unroll
    for (int off = 16; off > 0; off >>= 1) {
        sumv += __shfl_down_sync(0xFFFFFFFFu, sumv, off);
        maxv  = fmaxf(maxv, __shfl_down_sync(0xFFFFFFFFu, maxv, off));
    }

    __shared__ float ssum[THREADS1 / 32];
    __shared__ float smax[THREADS1 / 32];
    if (lane == 0) { ssum[wid] = sumv; smax[wid] = maxv; }
    __syncthreads();

    if (wid == 0) {
        float s2 = (lane < THREADS1 / 32) ? ssum[lane] : 0.0f;
        float m2 = (lane < THREADS1 / 32) ? smax[lane] : -CUDART_INF_F;
#pragma unroll
        for (int off = 4; off > 0; off >>= 1) {
            s2 += __shfl_down_sync(0xFFFFFFFFu, s2, off);
            m2  = fmaxf(m2, __shfl_down_sync(0xFFFFFFFFu, m2, off));
        }
        if (lane == 0) {
            g_psum[blockIdx.x] = s2;
            g_pmax[blockIdx.x] = m2;
        }
    }

    // ---- fused finish: last block reduces all partials ----
    __shared__ bool is_last;
    __syncthreads();
    if (tid == 0) {
        __threadfence();        // publish this block's partials
        unsigned int old = atomicAdd(&g_count, 1u);
        is_last = (old == (unsigned int)(BLOCKS1 - 1));
    }
    __syncthreads();

    if (is_last) {
        if (tid == 0) __threadfence();  // acquire: see all partials
        __syncthreads();
        float s = 0.0f;
        float m = -CUDART_INF_F;
#pragma unroll
        for (int i = 0; i < BLOCKS1 / THREADS1; i++) {
            const int idx = tid + i * THREADS1;
            s += __ldcg(&g_psum[idx]);
            m  = fmaxf(m, __ldcg(&g_pmax[idx]));
        }
#pragma unroll
        for (int off = 16; off > 0; off >>= 1) {
            s += __shfl_down_sync(0xFFFFFFFFu, s, off);
            m  = fmaxf(m, __shfl_down_sync(0xFFFFFFFFu, m, off));
        }
        if (lane == 0) { ssum[wid] = s; smax[wid] = m; }
        __syncthreads();
        if (wid == 0) {
            float s2 = (lane < THREADS1 / 32) ? ssum[lane] : 0.0f;
            float m2 = (lane < THREADS1 / 32) ? smax[lane] : -CUDART_INF_F;
#pragma unroll
            for (int off = 4; off > 0; off >>= 1) {
                s2 += __shfl_down_sync(0xFFFFFFFFu, s2, off);
                m2  = fmaxf(m2, __shfl_down_sync(0xFFFFFFFFu, m2, off));
            }
            if (lane == 0) {
                const float mean = s2 * (1.0f / (float)PIX);
                out[0] = (m2 > T1_CLIP_F) ? 0.0f : mean;
                g_count = 0;   // reset ticket for next graph replay
            }
        }
    }
}

extern "C" void kernel_launch(void* const* d_in, const int* in_sizes, int n_in,
                              void* d_out, int out_size)
{
    // Input order per reference: target, mu, sigma_mu, sigma_n, sigma_y
    const float* target  = (const float*)d_in[0];
    const float* mu      = (const float*)d_in[1];
    const float* sigma_y = (const float*)d_in[4];
    float* out = (float*)d_out;

    maploss_main<<<BLOCKS1, THREADS1>>>(target, mu, sigma_y, out);
}